// round 2
// baseline (speedup 1.0000x reference)
#include <cuda_runtime.h>
#include <cstdint>

#define NIMG 32          // 16 ref + 16 tgt
#define B_   16
#define H_   512
#define W_   512
#define HW_  (H_*W_)

// ---------------- scratch (device globals: allocation-free) ----------------
__device__ float         g_lum[NIMG * HW_];   // 33.5 MB
__device__ unsigned char g_e  [NIMG * HW_];   // 8.4 MB
__device__ unsigned char g_d  [NIMG * HW_];   // 8.4 MB
__device__ float         g_acc[NIMG * 4];     // vp_sum, np, vb_sum, nb
__device__ float         g_flag[NIMG];

// ---------------- K0: zero accumulators ----------------
__global__ void k_zero()
{
    int t = threadIdx.x;
    if (t < NIMG * 4) g_acc[t] = 0.f;
}

// ---------------- K1: luminance + Sobel + edge threshold ----------------
// block (32,8), tile 32x32 (4 rows/thread), halo 1
__global__ void k_lum_sobel(const float* __restrict__ ref, const float* __restrict__ tgt)
{
    const int img = blockIdx.z;
    const float* src = (img < B_) ? (ref + (size_t)img * 3 * HW_)
                                  : (tgt + (size_t)(img - B_) * 3 * HW_);
    __shared__ float sl[34][36];

    const int tx0 = blockIdx.x * 32, ty0 = blockIdx.y * 32;
    const int tid = threadIdx.y * 32 + threadIdx.x;

    for (int idx = tid; idx < 34 * 34; idx += 256) {
        int sy = idx / 34, sx = idx % 34;
        int gy = ty0 - 1 + sy, gx = tx0 - 1 + sx;
        float v = 0.f;
        if (gy >= 0 && gy < H_ && gx >= 0 && gx < W_) {
            int p = gy * W_ + gx;
            v = 0.299f * src[p] + 0.587f * src[HW_ + p] + 0.114f * src[2 * HW_ + p];
        }
        sl[sy][sx] = v;
    }
    __syncthreads();

    float*         lum_out = g_lum + (size_t)img * HW_;
    unsigned char* e_out   = g_e   + (size_t)img * HW_;

#pragma unroll
    for (int k = 0; k < 4; k++) {
        int yl = threadIdx.y + 8 * k;
        int xl = threadIdx.x;
        float a00 = sl[yl  ][xl], a01 = sl[yl  ][xl+1], a02 = sl[yl  ][xl+2];
        float a10 = sl[yl+1][xl],                        a12 = sl[yl+1][xl+2];
        float a20 = sl[yl+2][xl], a21 = sl[yl+2][xl+1], a22 = sl[yl+2][xl+2];
        float gxv = (a02 - a00) + 2.f * (a12 - a10) + (a22 - a20);
        float gyv = (a20 - a00) + 2.f * (a21 - a01) + (a22 - a02);
        // grad = sqrt(gx^2+gy^2+1e-12) > 0.1  <=>  gx^2+gy^2+1e-12 > 0.01
        float g2  = gxv * gxv + gyv * gyv + 1e-12f;
        int p = (ty0 + yl) * W_ + (tx0 + xl);
        lum_out[p] = sl[yl + 1][xl + 1];
        e_out[p]   = (g2 > 0.01f) ? (unsigned char)1 : (unsigned char)0;
    }
}

// ---------------- K2: 5x5 dilation (separable OR) ----------------
__global__ void k_dilate()
{
    const int img = blockIdx.z;
    __shared__ unsigned char se[36][40];
    __shared__ unsigned char sv[32][40];

    const int tx0 = blockIdx.x * 32, ty0 = blockIdx.y * 32;
    const int tid = threadIdx.y * 32 + threadIdx.x;
    const unsigned char* e = g_e + (size_t)img * HW_;

    for (int idx = tid; idx < 36 * 36; idx += 256) {
        int sy = idx / 36, sx = idx % 36;
        int gy = ty0 - 2 + sy, gx = tx0 - 2 + sx;
        unsigned char v = 0;
        if (gy >= 0 && gy < H_ && gx >= 0 && gx < W_) v = e[gy * W_ + gx];
        se[sy][sx] = v;
    }
    __syncthreads();
    for (int idx = tid; idx < 32 * 36; idx += 256) {
        int sy = idx / 36, sx = idx % 36;
        sv[sy][sx] = (unsigned char)(se[sy][sx] | se[sy+1][sx] | se[sy+2][sx] |
                                     se[sy+3][sx] | se[sy+4][sx]);
    }
    __syncthreads();

    unsigned char* dout = g_d + (size_t)img * HW_;
#pragma unroll
    for (int k = 0; k < 4; k++) {
        int yl = threadIdx.y + 8 * k, xl = threadIdx.x;
        unsigned char v = (unsigned char)(sv[yl][xl] | sv[yl][xl+1] | sv[yl][xl+2] |
                                          sv[yl][xl+3] | sv[yl][xl+4]);
        dout[(ty0 + yl) * W_ + (tx0 + xl)] = v;
    }
}

// ---------------- K3: fused 7x7 box variance + per-image reduction ----------------
// Column streaming: 134 active threads own columns x0-3 .. x0+130.
// Vertical 7-row box sum kept incrementally with a register ring (static indices
// via full unroll of the inner 7-step loop); horizontal 7-tap via smem row buffer.
// grid (4 strips, 8 row-chunks of 64, 32 images), blockDim 160.
__global__ __launch_bounds__(160) void k_variance()
{
    const int img = blockIdx.z;
    const int x0  = blockIdx.x * 128;
    const int y0  = blockIdx.y * 64;
    const int t   = threadIdx.x;

    const bool colActive = (t < 134);
    const int  gx        = x0 - 3 + t;
    const bool colValid  = colActive && (gx >= 0) && (gx < W_);

    const float*         lum = g_lum + (size_t)img * HW_;
    const unsigned char* ee  = g_e   + (size_t)img * HW_;
    const unsigned char* dd  = g_d   + (size_t)img * HW_;

    float hist[6][7];
#pragma unroll
    for (int q = 0; q < 6; q++)
#pragma unroll
        for (int s = 0; s < 7; s++) hist[q][s] = 0.f;

    float vs0 = 0, vs1 = 0, vs2 = 0, vs3 = 0, vs4 = 0, vs5 = 0;
    float accVp = 0, accNp = 0, accVb = 0, accNb = 0;

    __shared__ float vsm[6][144];

#pragma unroll 1
    for (int outer = 0; outer < 10; outer++) {
#pragma unroll
        for (int j = 0; j < 7; j++) {
            const int i = outer * 7 + j;    // input step index 0..69
            const int r = y0 - 3 + i;       // input row

            float x = 0.f, ef = 0.f, df = 0.f;
            bool  inb = colValid && (r >= 0) && (r < H_);
            if (inb) {
                int p = r * W_ + gx;
                x  = lum[p];
                ef = (float)ee[p];
                df = (float)dd[p];
            }
            float mp = df - ef;                 // 0 when OOB
            float mb = inb ? (1.f - df) : 0.f;  // zero-padding!
            float xx = x * x;
            float q0 = mp, q1 = x * mp, q2 = xx * mp;
            float q3 = mb, q4 = x * mb, q5 = xx * mb;

            vs0 += q0 - hist[0][j]; hist[0][j] = q0;
            vs1 += q1 - hist[1][j]; hist[1][j] = q1;
            vs2 += q2 - hist[2][j]; hist[2][j] = q2;
            vs3 += q3 - hist[3][j]; hist[3][j] = q3;
            vs4 += q4 - hist[4][j]; hist[4][j] = q4;
            vs5 += q5 - hist[5][j]; hist[5][j] = q5;

            if (i >= 6) {   // uniform condition across the block
                if (colActive) {
                    vsm[0][t] = vs0; vsm[1][t] = vs1; vsm[2][t] = vs2;
                    vsm[3][t] = vs3; vsm[4][t] = vs4; vsm[5][t] = vs5;
                }
                __syncthreads();
                if (t >= 3 && t < 131) {
                    float S0p = 0, S1p = 0, S2p = 0, S0b = 0, S1b = 0, S2b = 0;
#pragma unroll
                    for (int k = -3; k <= 3; k++) {
                        S0p += vsm[0][t + k]; S1p += vsm[1][t + k]; S2p += vsm[2][t + k];
                        S0b += vsm[3][t + k]; S1b += vsm[4][t + k]; S2b += vsm[5][t + k];
                    }
                    float cp   = fmaxf(S0p, 1.f);
                    float mup  = S1p / cp;
                    float varp = fmaxf(S2p / cp - mup * mup, 0.f);
                    float cb   = fmaxf(S0b, 1.f);
                    float mub  = S1b / cb;
                    float varb = fmaxf(S2b / cb - mub * mub, 0.f);
                    // center-row (y = r-3) mask values live in ring slot (j+4)%7
                    float mpc = hist[0][(j + 4) % 7];
                    float mbc = hist[3][(j + 4) % 7];
                    accVp += mpc * varp; accNp += mpc;
                    accVb += mbc * varb; accNb += mbc;
                }
                __syncthreads();
            }
        }
    }

    // warp reduce + one atomic per warp per scalar
#pragma unroll
    for (int off = 16; off > 0; off >>= 1) {
        accVp += __shfl_down_sync(0xffffffff, accVp, off);
        accNp += __shfl_down_sync(0xffffffff, accNp, off);
        accVb += __shfl_down_sync(0xffffffff, accVb, off);
        accNb += __shfl_down_sync(0xffffffff, accNb, off);
    }
    if ((t & 31) == 0) {
        atomicAdd(&g_acc[img * 4 + 0], accVp);
        atomicAdd(&g_acc[img * 4 + 1], accNp);
        atomicAdd(&g_acc[img * 4 + 2], accVb);
        atomicAdd(&g_acc[img * 4 + 3], accNb);
    }
}

// ---------------- K4: per-image ringing flag ----------------
__global__ void k_flag()
{
    int i = threadIdx.x;
    if (i < NIMG) {
        float vp = g_acc[i * 4 + 0], np = g_acc[i * 4 + 1];
        float vb = g_acc[i * 4 + 2], nb = g_acc[i * 4 + 3];
        float var_prox = vp / fmaxf(np, 1.f);
        float var_bg   = vb / fmaxf(nb, 1.f);
        g_flag[i] = (var_prox / (var_bg + 1e-12f) > 2.0f) ? 1.f : 0.f;
    }
}

// ---------------- K5: output = clip(ringing_tgt - ringing_ref, 0) ----------------
__global__ void k_output(float* __restrict__ out)
{
    int idx = blockIdx.x * blockDim.x + threadIdx.x;
    const int n4 = B_ * HW_ / 4;
    if (idx >= n4) return;
    int b  = idx / (HW_ / 4);
    int p4 = idx % (HW_ / 4);

    const uchar4* er = (const uchar4*)(g_e + (size_t)b * HW_);
    const uchar4* dr = (const uchar4*)(g_d + (size_t)b * HW_);
    const uchar4* et = (const uchar4*)(g_e + (size_t)(b + B_) * HW_);
    const uchar4* dt = (const uchar4*)(g_d + (size_t)(b + B_) * HW_);
    float fr = g_flag[b], ft = g_flag[b + B_];

    uchar4 e0 = er[p4], d0 = dr[p4], e1 = et[p4], d1 = dt[p4];
    float4 o;
    o.x = fmaxf((float)(d1.x - e1.x) * ft - (float)(d0.x - e0.x) * fr, 0.f);
    o.y = fmaxf((float)(d1.y - e1.y) * ft - (float)(d0.y - e0.y) * fr, 0.f);
    o.z = fmaxf((float)(d1.z - e1.z) * ft - (float)(d0.z - e0.z) * fr, 0.f);
    o.w = fmaxf((float)(d1.w - e1.w) * ft - (float)(d0.w - e0.w) * fr, 0.f);
    ((float4*)out)[idx] = o;
}

// ---------------- launch ----------------
extern "C" void kernel_launch(void* const* d_in, const int* in_sizes, int n_in,
                              void* d_out, int out_size)
{
    const float* ref = (const float*)d_in[0];
    const float* tgt = (const float*)d_in[1];

    k_zero<<<1, 128>>>();

    dim3 b1(32, 8);
    dim3 g1(W_ / 32, H_ / 32, NIMG);
    k_lum_sobel<<<g1, b1>>>(ref, tgt);
    k_dilate<<<g1, b1>>>();

    k_variance<<<dim3(4, 8, NIMG), 160>>>();
    k_flag<<<1, 32>>>();

    const int n4 = B_ * HW_ / 4;
    k_output<<<(n4 + 255) / 256, 256>>>((float*)d_out);
}

// round 3
// speedup vs baseline: 2.0128x; 2.0128x over previous
#include <cuda_runtime.h>
#include <cstdint>

#define NIMG 32          // 16 ref + 16 tgt
#define B_   16
#define H_   512
#define W_   512
#define HW_  (H_*W_)

// ---------------- scratch (device globals: allocation-free) ----------------
__device__ float         g_lum[NIMG * HW_];   // 33.5 MB
__device__ unsigned char g_e  [NIMG * HW_];   // 8.4 MB
__device__ unsigned char g_d  [NIMG * HW_];   // 8.4 MB
__device__ float         g_acc[NIMG * 4];     // vp_sum, np, vb_sum, nb
__device__ float         g_flag[NIMG];

// ---------------- K0: zero accumulators ----------------
__global__ void k_zero()
{
    int t = threadIdx.x;
    if (t < NIMG * 4) g_acc[t] = 0.f;
}

// ---------------- K1: luminance + Sobel + edge threshold ----------------
__global__ void k_lum_sobel(const float* __restrict__ ref, const float* __restrict__ tgt)
{
    const int img = blockIdx.z;
    const float* src = (img < B_) ? (ref + (size_t)img * 3 * HW_)
                                  : (tgt + (size_t)(img - B_) * 3 * HW_);
    __shared__ float sl[34][36];

    const int tx0 = blockIdx.x * 32, ty0 = blockIdx.y * 32;
    const int tid = threadIdx.y * 32 + threadIdx.x;

    for (int idx = tid; idx < 34 * 34; idx += 256) {
        int sy = idx / 34, sx = idx % 34;
        int gy = ty0 - 1 + sy, gx = tx0 - 1 + sx;
        float v = 0.f;
        if (gy >= 0 && gy < H_ && gx >= 0 && gx < W_) {
            int p = gy * W_ + gx;
            v = 0.299f * src[p] + 0.587f * src[HW_ + p] + 0.114f * src[2 * HW_ + p];
        }
        sl[sy][sx] = v;
    }
    __syncthreads();

    float*         lum_out = g_lum + (size_t)img * HW_;
    unsigned char* e_out   = g_e   + (size_t)img * HW_;

#pragma unroll
    for (int k = 0; k < 4; k++) {
        int yl = threadIdx.y + 8 * k;
        int xl = threadIdx.x;
        float a00 = sl[yl  ][xl], a01 = sl[yl  ][xl+1], a02 = sl[yl  ][xl+2];
        float a10 = sl[yl+1][xl],                        a12 = sl[yl+1][xl+2];
        float a20 = sl[yl+2][xl], a21 = sl[yl+2][xl+1], a22 = sl[yl+2][xl+2];
        float gxv = (a02 - a00) + 2.f * (a12 - a10) + (a22 - a20);
        float gyv = (a20 - a00) + 2.f * (a21 - a01) + (a22 - a02);
        float g2  = gxv * gxv + gyv * gyv + 1e-12f;   // sqrt(g2)>0.1 <=> g2>0.01
        int p = (ty0 + yl) * W_ + (tx0 + xl);
        lum_out[p] = sl[yl + 1][xl + 1];
        e_out[p]   = (g2 > 0.01f) ? (unsigned char)1 : (unsigned char)0;
    }
}

// ---------------- K2: 5x5 dilation (separable OR) ----------------
__global__ void k_dilate()
{
    const int img = blockIdx.z;
    __shared__ unsigned char se[36][40];
    __shared__ unsigned char sv[32][40];

    const int tx0 = blockIdx.x * 32, ty0 = blockIdx.y * 32;
    const int tid = threadIdx.y * 32 + threadIdx.x;
    const unsigned char* e = g_e + (size_t)img * HW_;

    for (int idx = tid; idx < 36 * 36; idx += 256) {
        int sy = idx / 36, sx = idx % 36;
        int gy = ty0 - 2 + sy, gx = tx0 - 2 + sx;
        unsigned char v = 0;
        if (gy >= 0 && gy < H_ && gx >= 0 && gx < W_) v = e[gy * W_ + gx];
        se[sy][sx] = v;
    }
    __syncthreads();
    for (int idx = tid; idx < 32 * 36; idx += 256) {
        int sy = idx / 36, sx = idx % 36;
        sv[sy][sx] = (unsigned char)(se[sy][sx] | se[sy+1][sx] | se[sy+2][sx] |
                                     se[sy+3][sx] | se[sy+4][sx]);
    }
    __syncthreads();

    unsigned char* dout = g_d + (size_t)img * HW_;
#pragma unroll
    for (int k = 0; k < 4; k++) {
        int yl = threadIdx.y + 8 * k, xl = threadIdx.x;
        unsigned char v = (unsigned char)(sv[yl][xl] | sv[yl][xl+1] | sv[yl][xl+2] |
                                          sv[yl][xl+3] | sv[yl][xl+4]);
        dout[(ty0 + yl) * W_ + (tx0 + xl)] = v;
    }
}

// ---------------- K3: fused 7x7 box variance + per-image reduction ----------------
// Warp-autonomous rewrite: thread owns 4 contiguous columns; block of 128 covers
// the full 512-px width. Vertical 7-row running sums in registers (e/d ring in
// packed uints; departing lum row re-fetched from L1). Horizontal 7-tap via
// intra-warp prefix/suffix shuffles; warp-boundary halo (3 cols each side) via
// tiny parity-double-buffered smem + ONE __syncthreads per output row.
// grid (16 row-strips of 32, 32 images), block 128.
#define ROWS_IN 38   // 32 output rows + 6 halo rows
__global__ __launch_bounds__(128) void k_variance()
{
    const int img = blockIdx.y;
    const int y0  = blockIdx.x * 32;
    const int t   = threadIdx.x;
    const int w   = t >> 5, l = t & 31;
    const int c0  = t * 4;

    const float*         lum = g_lum + (size_t)img * HW_;
    const unsigned char* ee  = g_e   + (size_t)img * HW_;
    const unsigned char* dd  = g_d   + (size_t)img * HW_;

    // e/d ring (packed uchar4); OOB rows substituted with e=d=1 so all q's = 0
    unsigned er[7], dr[7];
#pragma unroll
    for (int s = 0; s < 7; s++) { er[s] = 0x01010101u; dr[s] = 0x01010101u; }

    float vs[6][4];
#pragma unroll
    for (int q = 0; q < 6; q++)
#pragma unroll
        for (int c = 0; c < 4; c++) vs[q][c] = 0.f;

    float accVp = 0.f, accNp = 0.f, accVb = 0.f, accNb = 0.f;

    __shared__ float sufB[2][4][6][3];   // lane31 of warp w -> lane0 of warp w+1
    __shared__ float preB[2][4][6][3];   // lane0  of warp w -> lane31 of warp w-1

#pragma unroll 1
    for (int outer = 0; outer < 6; outer++) {
#pragma unroll
        for (int j = 0; j < 7; j++) {
            const int i = outer * 7 + j;
            if (i >= ROWS_IN) break;              // uniform
            const int r = y0 - 3 + i;

            // ---- load new row ----
            float4   xv = make_float4(0.f, 0.f, 0.f, 0.f);
            unsigned eu = 0x01010101u, du = 0x01010101u;
            const bool inb = (r >= 0) && (r < H_);
            if (inb) {
                xv = *(const float4*)(lum + r * W_ + c0);
                eu = *(const unsigned*)(ee + r * W_ + c0);
                du = *(const unsigned*)(dd + r * W_ + c0);
            }
            // ---- re-load departing row (r-7), same substitution rule ----
            const int ro = r - 7;
            float4 xo4 = make_float4(0.f, 0.f, 0.f, 0.f);
            if (ro >= 0 && ro < H_)
                xo4 = *(const float4*)(lum + ro * W_ + c0);

            // ---- vertical running-sum update ----
#pragma unroll
            for (int c = 0; c < 4; c++) {
                float xn  = (&xv.x)[c];
                float en  = (float)((eu >> (8 * c)) & 1u);
                float dn  = (float)((du >> (8 * c)) & 1u);
                float mpn = dn - en;
                float mbn = 1.f - dn;
                float xo  = (&xo4.x)[c];
                float eo  = (float)((er[j] >> (8 * c)) & 1u);
                float dof = (float)((dr[j] >> (8 * c)) & 1u);
                float mpo = dof - eo;
                float mbo = 1.f - dof;
                vs[0][c] += mpn - mpo;
                vs[1][c] += xn * mpn - xo * mpo;
                vs[2][c] += xn * xn * mpn - xo * xo * mpo;
                vs[3][c] += mbn - mbo;
                vs[4][c] += xn * mbn - xo * mbo;
                vs[5][c] += xn * xn * mbn - xo * xo * mbo;
            }
            er[j] = eu; dr[j] = du;

            if (i >= 6) {
                const int par = i & 1;
                // ---- per-quantity in-lane prefixes ----
                float p0[6], p1[6], p2[6], T[6];
#pragma unroll
                for (int q = 0; q < 6; q++) {
                    p0[q] = vs[q][0];
                    p1[q] = p0[q] + vs[q][1];
                    p2[q] = p1[q] + vs[q][2];
                    T[q]  = p2[q] + vs[q][3];
                }
                // ---- publish warp-boundary halos ----
                if (l == 31) {
#pragma unroll
                    for (int q = 0; q < 6; q++) {
                        sufB[par][w][q][0] = T[q] - p0[q];
                        sufB[par][w][q][1] = T[q] - p1[q];
                        sufB[par][w][q][2] = T[q] - p2[q];
                    }
                }
                if (l == 0) {
#pragma unroll
                    for (int q = 0; q < 6; q++) {
                        preB[par][w][q][0] = p0[q];
                        preB[par][w][q][1] = p1[q];
                        preB[par][w][q][2] = p2[q];
                    }
                }
                __syncthreads();

                // ---- horizontal 7-tap via shuffles ----
                float Wn[6][4];
#pragma unroll
                for (int q = 0; q < 6; q++) {
                    float s1 = T[q] - p0[q];
                    float s2 = T[q] - p1[q];
                    float s3 = T[q] - p2[q];
                    float ls1 = __shfl_up_sync(0xffffffffu, s1, 1);
                    float ls2 = __shfl_up_sync(0xffffffffu, s2, 1);
                    float ls3 = __shfl_up_sync(0xffffffffu, s3, 1);
                    float rp0 = __shfl_down_sync(0xffffffffu, p0[q], 1);
                    float rp1 = __shfl_down_sync(0xffffffffu, p1[q], 1);
                    float rp2 = __shfl_down_sync(0xffffffffu, p2[q], 1);
                    if (l == 0) {
                        ls1 = (w > 0) ? sufB[par][w - 1][q][0] : 0.f;
                        ls2 = (w > 0) ? sufB[par][w - 1][q][1] : 0.f;
                        ls3 = (w > 0) ? sufB[par][w - 1][q][2] : 0.f;
                    }
                    if (l == 31) {
                        rp0 = (w < 3) ? preB[par][w + 1][q][0] : 0.f;
                        rp1 = (w < 3) ? preB[par][w + 1][q][1] : 0.f;
                        rp2 = (w < 3) ? preB[par][w + 1][q][2] : 0.f;
                    }
                    Wn[q][0] = ls1 + T[q];
                    Wn[q][1] = ls2 + T[q] + rp0;
                    Wn[q][2] = ls3 + T[q] + rp1;
                    Wn[q][3] = T[q] + rp2;
                }

                // ---- variance + masked accumulate (center row in slot (j+4)%7) ----
                const int jc = (j + 4) % 7;
#pragma unroll
                for (int c = 0; c < 4; c++) {
                    float cp   = fmaxf(Wn[0][c], 1.f);
                    float rcp_ = __fdividef(1.f, cp);
                    float mup  = Wn[1][c] * rcp_;
                    float varp = fmaxf(Wn[2][c] * rcp_ - mup * mup, 0.f);
                    float cb   = fmaxf(Wn[3][c], 1.f);
                    float rcb  = __fdividef(1.f, cb);
                    float mub  = Wn[4][c] * rcb;
                    float varb = fmaxf(Wn[5][c] * rcb - mub * mub, 0.f);
                    float ecf  = (float)((er[jc] >> (8 * c)) & 1u);
                    float dcf  = (float)((dr[jc] >> (8 * c)) & 1u);
                    float mpc  = dcf - ecf;
                    float mbc  = 1.f - dcf;
                    accVp += mpc * varp; accNp += mpc;
                    accVb += mbc * varb; accNb += mbc;
                }
            }
        }
    }

    // warp reduce + one atomic per warp per scalar
#pragma unroll
    for (int off = 16; off > 0; off >>= 1) {
        accVp += __shfl_down_sync(0xffffffffu, accVp, off);
        accNp += __shfl_down_sync(0xffffffffu, accNp, off);
        accVb += __shfl_down_sync(0xffffffffu, accVb, off);
        accNb += __shfl_down_sync(0xffffffffu, accNb, off);
    }
    if (l == 0) {
        atomicAdd(&g_acc[img * 4 + 0], accVp);
        atomicAdd(&g_acc[img * 4 + 1], accNp);
        atomicAdd(&g_acc[img * 4 + 2], accVb);
        atomicAdd(&g_acc[img * 4 + 3], accNb);
    }
}

// ---------------- K4: per-image ringing flag ----------------
__global__ void k_flag()
{
    int i = threadIdx.x;
    if (i < NIMG) {
        float vp = g_acc[i * 4 + 0], np = g_acc[i * 4 + 1];
        float vb = g_acc[i * 4 + 2], nb = g_acc[i * 4 + 3];
        float var_prox = vp / fmaxf(np, 1.f);
        float var_bg   = vb / fmaxf(nb, 1.f);
        g_flag[i] = (var_prox / (var_bg + 1e-12f) > 2.0f) ? 1.f : 0.f;
    }
}

// ---------------- K5: output = clip(ringing_tgt - ringing_ref, 0) ----------------
__global__ void k_output(float* __restrict__ out)
{
    int idx = blockIdx.x * blockDim.x + threadIdx.x;
    const int n4 = B_ * HW_ / 4;
    if (idx >= n4) return;
    int b  = idx / (HW_ / 4);
    int p4 = idx % (HW_ / 4);

    const uchar4* er = (const uchar4*)(g_e + (size_t)b * HW_);
    const uchar4* dr = (const uchar4*)(g_d + (size_t)b * HW_);
    const uchar4* et = (const uchar4*)(g_e + (size_t)(b + B_) * HW_);
    const uchar4* dt = (const uchar4*)(g_d + (size_t)(b + B_) * HW_);
    float fr = g_flag[b], ft = g_flag[b + B_];

    uchar4 e0 = er[p4], d0 = dr[p4], e1 = et[p4], d1 = dt[p4];
    float4 o;
    o.x = fmaxf((float)(d1.x - e1.x) * ft - (float)(d0.x - e0.x) * fr, 0.f);
    o.y = fmaxf((float)(d1.y - e1.y) * ft - (float)(d0.y - e0.y) * fr, 0.f);
    o.z = fmaxf((float)(d1.z - e1.z) * ft - (float)(d0.z - e0.z) * fr, 0.f);
    o.w = fmaxf((float)(d1.w - e1.w) * ft - (float)(d0.w - e0.w) * fr, 0.f);
    ((float4*)out)[idx] = o;
}

// ---------------- launch ----------------
extern "C" void kernel_launch(void* const* d_in, const int* in_sizes, int n_in,
                              void* d_out, int out_size)
{
    const float* ref = (const float*)d_in[0];
    const float* tgt = (const float*)d_in[1];

    k_zero<<<1, 128>>>();

    dim3 b1(32, 8);
    dim3 g1(W_ / 32, H_ / 32, NIMG);
    k_lum_sobel<<<g1, b1>>>(ref, tgt);
    k_dilate<<<g1, b1>>>();

    k_variance<<<dim3(16, NIMG), 128>>>();
    k_flag<<<1, 32>>>();

    const int n4 = B_ * HW_ / 4;
    k_output<<<(n4 + 255) / 256, 256>>>((float*)d_out);
}

// round 4
// speedup vs baseline: 2.2191x; 1.1025x over previous
#include <cuda_runtime.h>
#include <cstdint>

#define NIMG 32          // 16 ref + 16 tgt
#define B_   16
#define H_   512
#define W_   512
#define HW_  (H_*W_)

// ---------------- scratch (device globals: allocation-free) ----------------
__device__ float         g_lum[NIMG * HW_];   // 33.5 MB
__device__ unsigned char g_e  [NIMG * HW_];   // 8.4 MB
__device__ unsigned char g_d  [NIMG * HW_];   // 8.4 MB
__device__ float         g_acc[NIMG * 4];     // vp_sum, np, vb_sum, nb
__device__ float         g_flag[NIMG];

// ---------------- K0: zero accumulators ----------------
__global__ void k_zero()
{
    int t = threadIdx.x;
    if (t < NIMG * 4) g_acc[t] = 0.f;
}

// ---------------- K1+K2 fused: luminance + Sobel + edge + 5x5 dilation ------
// block (32,8), 32x32 output tile. lum smem halo 3; E smem halo 2 (OOB => 0,
// matching -inf-padded reduce_window); separable OR dilation.
__global__ void k_edges(const float* __restrict__ ref, const float* __restrict__ tgt)
{
    const int img = blockIdx.z;
    const float* src = (img < B_) ? (ref + (size_t)img * 3 * HW_)
                                  : (tgt + (size_t)(img - B_) * 3 * HW_);
    __shared__ float         sl[38][40];
    __shared__ unsigned char se[36][40];
    __shared__ unsigned char sv[32][40];

    const int tx0 = blockIdx.x * 32, ty0 = blockIdx.y * 32;
    const int tid = threadIdx.y * 32 + threadIdx.x;

    // lum with halo 3 (zero-padded, matches SAME conv)
    for (int idx = tid; idx < 38 * 38; idx += 256) {
        int sy = idx / 38, sx = idx % 38;
        int gy = ty0 - 3 + sy, gx = tx0 - 3 + sx;
        float v = 0.f;
        if (gy >= 0 && gy < H_ && gx >= 0 && gx < W_) {
            int p = gy * W_ + gx;
            v = 0.299f * src[p] + 0.587f * src[HW_ + p] + 0.114f * src[2 * HW_ + p];
        }
        sl[sy][sx] = v;
    }
    __syncthreads();

    // E with halo 2; OOB pixels forced to 0 (dilation only sees in-image E)
    for (int idx = tid; idx < 36 * 36; idx += 256) {
        int ey = idx / 36, ex = idx % 36;
        int gy = ty0 - 2 + ey, gx = tx0 - 2 + ex;
        unsigned char ev = 0;
        if (gy >= 0 && gy < H_ && gx >= 0 && gx < W_) {
            float a00 = sl[ey  ][ex], a01 = sl[ey  ][ex+1], a02 = sl[ey  ][ex+2];
            float a10 = sl[ey+1][ex],                        a12 = sl[ey+1][ex+2];
            float a20 = sl[ey+2][ex], a21 = sl[ey+2][ex+1], a22 = sl[ey+2][ex+2];
            float gxv = (a02 - a00) + 2.f * (a12 - a10) + (a22 - a20);
            float gyv = (a20 - a00) + 2.f * (a21 - a01) + (a22 - a02);
            float g2  = gxv * gxv + gyv * gyv + 1e-12f;  // sqrt(g2)>0.1 <=> g2>0.01
            ev = (g2 > 0.01f) ? (unsigned char)1 : (unsigned char)0;
        }
        se[ey][ex] = ev;
    }
    __syncthreads();

    // vertical OR (5 rows)
    for (int idx = tid; idx < 32 * 36; idx += 256) {
        int y = idx / 36, ex = idx % 36;
        sv[y][ex] = (unsigned char)(se[y][ex] | se[y+1][ex] | se[y+2][ex] |
                                    se[y+3][ex] | se[y+4][ex]);
    }
    __syncthreads();

    float*         lum_out = g_lum + (size_t)img * HW_;
    unsigned char* e_out   = g_e   + (size_t)img * HW_;
    unsigned char* d_out   = g_d   + (size_t)img * HW_;

#pragma unroll
    for (int k = 0; k < 4; k++) {
        int yl = threadIdx.y + 8 * k, xl = threadIdx.x;
        unsigned char d = (unsigned char)(sv[yl][xl] | sv[yl][xl+1] | sv[yl][xl+2] |
                                          sv[yl][xl+3] | sv[yl][xl+4]);
        int p = (ty0 + yl) * W_ + (tx0 + xl);
        lum_out[p] = sl[yl + 3][xl + 3];
        e_out[p]   = se[yl + 2][xl + 2];
        d_out[p]   = d;
    }
}

// ---------------- K3: fused 7x7 box variance + per-image reduction ----------------
// Warp-autonomous, 4 cols/thread, full 512-px width per 128-thread block.
// NEW: software prefetch of the next input row hides L2 latency behind the
// vertical/horizontal compute of the current row. Departing row (r-7) is an
// L1 hit (read as "new" 7 iterations ago), loaded in place.
#define ROWS_IN 38   // 32 output rows + 6 halo rows
__global__ __launch_bounds__(128, 4) void k_variance()
{
    const int img = blockIdx.y;
    const int y0  = blockIdx.x * 32;
    const int t   = threadIdx.x;
    const int w   = t >> 5, l = t & 31;
    const int c0  = t * 4;

    const float*         lum = g_lum + (size_t)img * HW_;
    const unsigned char* ee  = g_e   + (size_t)img * HW_;
    const unsigned char* dd  = g_d   + (size_t)img * HW_;

    // e/d ring (packed uchar4); OOB rows substituted with e=d=1 so all q's = 0
    unsigned er[7], dr[7];
#pragma unroll
    for (int s = 0; s < 7; s++) { er[s] = 0x01010101u; dr[s] = 0x01010101u; }

    float vs[6][4];
#pragma unroll
    for (int q = 0; q < 6; q++)
#pragma unroll
        for (int c = 0; c < 4; c++) vs[q][c] = 0.f;

    float accVp = 0.f, accNp = 0.f, accVb = 0.f, accNb = 0.f;

    __shared__ float sufB[2][4][6][3];
    __shared__ float preB[2][4][6][3];

    // ---- preload row i=0 ----
    float4   xv = make_float4(0.f, 0.f, 0.f, 0.f);
    unsigned eu = 0x01010101u, du = 0x01010101u;
    {
        const int r0 = y0 - 3;
        if (r0 >= 0 && r0 < H_) {
            xv = *(const float4*)(lum + r0 * W_ + c0);
            eu = *(const unsigned*)(ee + r0 * W_ + c0);
            du = *(const unsigned*)(dd + r0 * W_ + c0);
        }
    }

#pragma unroll 1
    for (int outer = 0; outer < 6; outer++) {
#pragma unroll
        for (int j = 0; j < 7; j++) {
            const int i = outer * 7 + j;
            if (i >= ROWS_IN) break;              // uniform
            const int r = y0 - 3 + i;

            // ---- prefetch row i+1 (hides L2 latency behind this row's work) ----
            float4   xvn = make_float4(0.f, 0.f, 0.f, 0.f);
            unsigned eun = 0x01010101u, dun = 0x01010101u;
            const int rn = r + 1;
            if (i + 1 < ROWS_IN && rn >= 0 && rn < H_) {
                xvn = *(const float4*)(lum + rn * W_ + c0);
                eun = *(const unsigned*)(ee + rn * W_ + c0);
                dun = *(const unsigned*)(dd + rn * W_ + c0);
            }

            // ---- departing row (r-7): L1 hit ----
            const int ro = r - 7;
            float4 xo4 = make_float4(0.f, 0.f, 0.f, 0.f);
            if (ro >= 0 && ro < H_)
                xo4 = *(const float4*)(lum + ro * W_ + c0);

            // ---- vertical running-sum update ----
#pragma unroll
            for (int c = 0; c < 4; c++) {
                float xn  = (&xv.x)[c];
                float en  = (float)((eu >> (8 * c)) & 1u);
                float dn  = (float)((du >> (8 * c)) & 1u);
                float mpn = dn - en;
                float mbn = 1.f - dn;
                float xo  = (&xo4.x)[c];
                float eo  = (float)((er[j] >> (8 * c)) & 1u);
                float dof = (float)((dr[j] >> (8 * c)) & 1u);
                float mpo = dof - eo;
                float mbo = 1.f - dof;
                vs[0][c] += mpn - mpo;
                vs[1][c] += xn * mpn - xo * mpo;
                vs[2][c] += xn * xn * mpn - xo * xo * mpo;
                vs[3][c] += mbn - mbo;
                vs[4][c] += xn * mbn - xo * mbo;
                vs[5][c] += xn * xn * mbn - xo * xo * mbo;
            }
            er[j] = eu; dr[j] = du;

            if (i >= 6) {
                const int par = i & 1;
                float p0[6], p1[6], p2[6], T[6];
#pragma unroll
                for (int q = 0; q < 6; q++) {
                    p0[q] = vs[q][0];
                    p1[q] = p0[q] + vs[q][1];
                    p2[q] = p1[q] + vs[q][2];
                    T[q]  = p2[q] + vs[q][3];
                }
                if (l == 31) {
#pragma unroll
                    for (int q = 0; q < 6; q++) {
                        sufB[par][w][q][0] = T[q] - p0[q];
                        sufB[par][w][q][1] = T[q] - p1[q];
                        sufB[par][w][q][2] = T[q] - p2[q];
                    }
                }
                if (l == 0) {
#pragma unroll
                    for (int q = 0; q < 6; q++) {
                        preB[par][w][q][0] = p0[q];
                        preB[par][w][q][1] = p1[q];
                        preB[par][w][q][2] = p2[q];
                    }
                }
                __syncthreads();

                float Wn[6][4];
#pragma unroll
                for (int q = 0; q < 6; q++) {
                    float s1 = T[q] - p0[q];
                    float s2 = T[q] - p1[q];
                    float s3 = T[q] - p2[q];
                    float ls1 = __shfl_up_sync(0xffffffffu, s1, 1);
                    float ls2 = __shfl_up_sync(0xffffffffu, s2, 1);
                    float ls3 = __shfl_up_sync(0xffffffffu, s3, 1);
                    float rp0 = __shfl_down_sync(0xffffffffu, p0[q], 1);
                    float rp1 = __shfl_down_sync(0xffffffffu, p1[q], 1);
                    float rp2 = __shfl_down_sync(0xffffffffu, p2[q], 1);
                    if (l == 0) {
                        ls1 = (w > 0) ? sufB[par][w - 1][q][0] : 0.f;
                        ls2 = (w > 0) ? sufB[par][w - 1][q][1] : 0.f;
                        ls3 = (w > 0) ? sufB[par][w - 1][q][2] : 0.f;
                    }
                    if (l == 31) {
                        rp0 = (w < 3) ? preB[par][w + 1][q][0] : 0.f;
                        rp1 = (w < 3) ? preB[par][w + 1][q][1] : 0.f;
                        rp2 = (w < 3) ? preB[par][w + 1][q][2] : 0.f;
                    }
                    Wn[q][0] = ls1 + T[q];
                    Wn[q][1] = ls2 + T[q] + rp0;
                    Wn[q][2] = ls3 + T[q] + rp1;
                    Wn[q][3] = T[q] + rp2;
                }

                const int jc = (j + 4) % 7;
#pragma unroll
                for (int c = 0; c < 4; c++) {
                    float cp   = fmaxf(Wn[0][c], 1.f);
                    float rcp_ = __fdividef(1.f, cp);
                    float mup  = Wn[1][c] * rcp_;
                    float varp = fmaxf(Wn[2][c] * rcp_ - mup * mup, 0.f);
                    float cb   = fmaxf(Wn[3][c], 1.f);
                    float rcb  = __fdividef(1.f, cb);
                    float mub  = Wn[4][c] * rcb;
                    float varb = fmaxf(Wn[5][c] * rcb - mub * mub, 0.f);
                    float ecf  = (float)((er[jc] >> (8 * c)) & 1u);
                    float dcf  = (float)((dr[jc] >> (8 * c)) & 1u);
                    float mpc  = dcf - ecf;
                    float mbc  = 1.f - dcf;
                    accVp += mpc * varp; accNp += mpc;
                    accVb += mbc * varb; accNb += mbc;
                }
            }

            xv = xvn; eu = eun; du = dun;
        }
    }

#pragma unroll
    for (int off = 16; off > 0; off >>= 1) {
        accVp += __shfl_down_sync(0xffffffffu, accVp, off);
        accNp += __shfl_down_sync(0xffffffffu, accNp, off);
        accVb += __shfl_down_sync(0xffffffffu, accVb, off);
        accNb += __shfl_down_sync(0xffffffffu, accNb, off);
    }
    if (l == 0) {
        atomicAdd(&g_acc[img * 4 + 0], accVp);
        atomicAdd(&g_acc[img * 4 + 1], accNp);
        atomicAdd(&g_acc[img * 4 + 2], accVb);
        atomicAdd(&g_acc[img * 4 + 3], accNb);
    }
}

// ---------------- K4: per-image ringing flag ----------------
__global__ void k_flag()
{
    int i = threadIdx.x;
    if (i < NIMG) {
        float vp = g_acc[i * 4 + 0], np = g_acc[i * 4 + 1];
        float vb = g_acc[i * 4 + 2], nb = g_acc[i * 4 + 3];
        float var_prox = vp / fmaxf(np, 1.f);
        float var_bg   = vb / fmaxf(nb, 1.f);
        g_flag[i] = (var_prox / (var_bg + 1e-12f) > 2.0f) ? 1.f : 0.f;
    }
}

// ---------------- K5: output = clip(ringing_tgt - ringing_ref, 0) ----------------
__global__ void k_output(float* __restrict__ out)
{
    int idx = blockIdx.x * blockDim.x + threadIdx.x;
    const int n4 = B_ * HW_ / 4;
    if (idx >= n4) return;
    int b  = idx / (HW_ / 4);
    int p4 = idx % (HW_ / 4);

    const uchar4* er = (const uchar4*)(g_e + (size_t)b * HW_);
    const uchar4* dr = (const uchar4*)(g_d + (size_t)b * HW_);
    const uchar4* et = (const uchar4*)(g_e + (size_t)(b + B_) * HW_);
    const uchar4* dt = (const uchar4*)(g_d + (size_t)(b + B_) * HW_);
    float fr = g_flag[b], ft = g_flag[b + B_];

    uchar4 e0 = er[p4], d0 = dr[p4], e1 = et[p4], d1 = dt[p4];
    float4 o;
    o.x = fmaxf((float)(d1.x - e1.x) * ft - (float)(d0.x - e0.x) * fr, 0.f);
    o.y = fmaxf((float)(d1.y - e1.y) * ft - (float)(d0.y - e0.y) * fr, 0.f);
    o.z = fmaxf((float)(d1.z - e1.z) * ft - (float)(d0.z - e0.z) * fr, 0.f);
    o.w = fmaxf((float)(d1.w - e1.w) * ft - (float)(d0.w - e0.w) * fr, 0.f);
    ((float4*)out)[idx] = o;
}

// ---------------- launch ----------------
extern "C" void kernel_launch(void* const* d_in, const int* in_sizes, int n_in,
                              void* d_out, int out_size)
{
    const float* ref = (const float*)d_in[0];
    const float* tgt = (const float*)d_in[1];

    k_zero<<<1, 128>>>();

    dim3 b1(32, 8);
    dim3 g1(W_ / 32, H_ / 32, NIMG);
    k_edges<<<g1, b1>>>(ref, tgt);

    k_variance<<<dim3(16, NIMG), 128>>>();
    k_flag<<<1, 32>>>();

    const int n4 = B_ * HW_ / 4;
    k_output<<<(n4 + 255) / 256, 256>>>((float*)d_out);
}